// round 1
// baseline (speedup 1.0000x reference)
#include <cuda_runtime.h>
#include <math.h>

#define BB 2
#define CC 128
#define HH 96
#define WW 160
#define HWHW (HH*WW)
#define NDG 16
#define NK2 9
#define CIN0P 392     // 388 padded to multiple of 8
#define COFF 432      // 27 * DG

// ---- device-global scratch (no allocations allowed) ----
__device__ float g_ef  [BB*CIN0P*HWHW];     // packed+padded concat input
__device__ float g_bufA[BB*CC*HWHW];        // h0 / h2
__device__ float g_bufB[BB*CC*HWHW];        // h1
__device__ float g_h3  [BB*COFF*HWHW];      // conv_offset output (432 ch)
__device__ float g_val [BB*CC*NK2*HWHW];    // gathered deform samples [b][ci*9+k][hw]
__device__ float g_w0p [CC*CIN0P*9];        // cw0 padded to 392 in-channels

// ---------------------------------------------------------------------------
// Pack ef = concat(extra_feat, flow_1, flow_2), pad channels 388..391 with 0
// ---------------------------------------------------------------------------
__global__ void pack_ef_k(const float* __restrict__ exf,
                          const float* __restrict__ f1,
                          const float* __restrict__ f2)
{
    int idx = blockIdx.x * 256 + threadIdx.x;
    if (idx >= BB*CIN0P*HWHW) return;
    int p = idx % HWHW;
    int c = (idx / HWHW) % CIN0P;
    int b = idx / (CIN0P*HWHW);
    float v = 0.f;
    if (c < 384)      v = exf[(b*384 + c)*HWHW + p];
    else if (c < 386) v = f1[(b*2 + (c-384))*HWHW + p];
    else if (c < 388) v = f2[(b*2 + (c-386))*HWHW + p];
    g_ef[idx] = v;
}

__global__ void pad_w0_k(const float* __restrict__ cw0)
{
    int idx = blockIdx.x * 256 + threadIdx.x;
    if (idx >= CC*CIN0P*9) return;
    int t  = idx % 9;
    int c  = (idx / 9) % CIN0P;
    int oc = idx / (CIN0P*9);
    g_w0p[idx] = (c < 388) ? cw0[(oc*388 + c)*9 + t] : 0.f;
}

// ---------------------------------------------------------------------------
// Register-tiled direct conv.  K=3 (pad 1) or K=1 (pointwise / GEMM).
// Tile: 64 out-channels x (8 rows x 16 cols) pixels, 8-in-channel chunks.
// 256 threads; each thread: 8 oc x 4 consecutive px accumulators.
// ---------------------------------------------------------------------------
template<int K, bool ACT>
__global__ void __launch_bounds__(256)
conv_k(const float* __restrict__ in, const float* __restrict__ wgt,
       const float* __restrict__ bias, float* __restrict__ out,
       int CIN, int COUT)
{
    constexpr int KK  = K*K;
    constexpr int TW  = 16, TH = 8, TOC = 64, CH = 8;
    constexpr int PW  = TW + K - 1;                 // 18 / 16
    constexpr int PH  = TH + K - 1;                 // 10 / 8
    constexpr int PWS = (K == 3) ? (PW + 3) : PW;   // 21 / 16 (bank-friendly)
    constexpr int WST = CH*KK + 1;                  // 73 / 9
    constexpr int PAD = (K == 3) ? 1 : 0;

    __shared__ float s_in[CH*PH*PWS];
    __shared__ float s_w [TOC*WST];

    const int tid  = threadIdx.x;
    const int oc_t = tid >> 5;          // 0..7
    const int px_t = tid & 31;
    const int r    = px_t >> 2;         // 0..7 (row in tile)
    const int c0   = (px_t & 3) << 2;   // 0,4,8,12 (col group)

    const int octiles = (COUT + TOC - 1) / TOC;
    const int b   = blockIdx.z / octiles;
    const int ocb = (blockIdx.z % octiles) * TOC;
    const int w0  = blockIdx.x * TW;
    const int h0  = blockIdx.y * TH;

    float acc[8][4];
    #pragma unroll
    for (int j = 0; j < 8; j++)
        #pragma unroll
        for (int p = 0; p < 4; p++) acc[j][p] = 0.f;

    const float* inb = in + (long)b * CIN * HWHW;

    for (int cc = 0; cc < CIN; cc += CH) {
        __syncthreads();
        // stage input patch
        #pragma unroll 1
        for (int idx = tid; idx < CH*PH*PW; idx += 256) {
            int ci  = idx / (PH*PW);
            int rem = idx - ci*(PH*PW);
            int pr  = rem / PW;
            int pc  = rem - pr*PW;
            int gh  = h0 - PAD + pr;
            int gw  = w0 - PAD + pc;
            float v = 0.f;
            if (gh >= 0 && gh < HH && gw >= 0 && gw < WW)
                v = inb[(cc + ci)*HWHW + gh*WW + gw];
            s_in[ci*(PH*PWS) + pr*PWS + pc] = v;
        }
        // stage weights [oc][ci*KK + tap], oc-major (conflict-free store)
        #pragma unroll 1
        for (int idx = tid; idx < TOC*CH*KK; idx += 256) {
            int oc = idx / (CH*KK);
            int rr = idx - oc*(CH*KK);
            float v = 0.f;
            if (ocb + oc < COUT)
                v = wgt[(long)(ocb + oc)*CIN*KK + cc*KK + rr];
            s_w[oc*WST + rr] = v;
        }
        __syncthreads();

        #pragma unroll 1
        for (int ci = 0; ci < CH; ci++) {
            const float* sw = &s_w[oc_t*8*WST + ci*KK];
            #pragma unroll
            for (int ky = 0; ky < K; ky++) {
                float iv[K + 3];
                const float* ib = &s_in[ci*(PH*PWS) + (r + ky)*PWS + c0];
                #pragma unroll
                for (int t = 0; t < K + 3; t++) iv[t] = ib[t];
                #pragma unroll
                for (int kx = 0; kx < K; kx++) {
                    #pragma unroll
                    for (int j = 0; j < 8; j++) {
                        float wv = sw[j*WST + ky*K + kx];
                        acc[j][0] = fmaf(wv, iv[kx+0], acc[j][0]);
                        acc[j][1] = fmaf(wv, iv[kx+1], acc[j][1]);
                        acc[j][2] = fmaf(wv, iv[kx+2], acc[j][2]);
                        acc[j][3] = fmaf(wv, iv[kx+3], acc[j][3]);
                    }
                }
            }
        }
    }

    // epilogue
    #pragma unroll
    for (int j = 0; j < 8; j++) {
        int oc = ocb + oc_t*8 + j;
        if (oc < COUT) {
            float bz = bias[oc];
            float4 o;
            float v0 = acc[j][0] + bz;
            float v1 = acc[j][1] + bz;
            float v2 = acc[j][2] + bz;
            float v3 = acc[j][3] + bz;
            if (ACT) {
                v0 = (v0 >= 0.f) ? v0 : 0.1f*v0;
                v1 = (v1 >= 0.f) ? v1 : 0.1f*v1;
                v2 = (v2 >= 0.f) ? v2 : 0.1f*v2;
                v3 = (v3 >= 0.f) ? v3 : 0.1f*v3;
            }
            o.x = v0; o.y = v1; o.z = v2; o.w = v3;
            *(float4*)&out[((long)(b*COUT + oc)*HH + (h0 + r))*WW + w0 + c0] = o;
        }
    }
}

// ---------------------------------------------------------------------------
// Deform gather: one thread per (b, dg, tap, h, w).
// Computes offset = 10*tanh(h3) + flow (channel-reversed tiling),
// mask = sigmoid(h3), bilinear-samples 8 channels of x, writes
// val[b][ci*9+k][h][w] with ci = dg*8+cg.
// ---------------------------------------------------------------------------
__global__ void gather_k(const float* __restrict__ x,
                         const float* __restrict__ f1,
                         const float* __restrict__ f2)
{
    int idx = blockIdx.x * 256 + threadIdx.x;
    if (idx >= BB*NDG*NK2*HWHW) return;

    int w = idx % WW;   int t = idx / WW;
    int h = t % HH;     t /= HH;
    int k = t % NK2;    t /= NK2;
    int dgi = t % NDG;
    int b   = t / NDG;

    int p = h*WW + w;
    const float* fl = (dgi < 8) ? f1 : f2;
    float fy = fl[(b*2 + 1)*HWHW + p];   // flow[:, ::-1]: comp0 <- channel 1
    float fx = fl[(b*2 + 0)*HWHW + p];

    int coff = (b*COFF + dgi*18 + k*2)*HWHW + p;
    float dy = 10.f * tanhf(g_h3[coff])        + fy;
    float dx = 10.f * tanhf(g_h3[coff + HWHW]) + fx;
    float mk = 1.f / (1.f + expf(-g_h3[(b*COFF + 288 + dgi*9 + k)*HWHW + p]));

    float py = dy + (float)h + (float)(k/3 - 1);
    float px = dx + (float)w + (float)(k%3 - 1);
    float y0f = floorf(py), x0f = floorf(px);
    float wy = py - y0f, wx = px - x0f;
    int y0 = (int)y0f, x0 = (int)x0f;

    bool vy0 = (y0   >= 0) && (y0   < HH);
    bool vy1 = (y0+1 >= 0) && (y0+1 < HH);
    bool vx0 = (x0   >= 0) && (x0   < WW);
    bool vx1 = (x0+1 >= 0) && (x0+1 < WW);

    int y0c = min(max(y0,   0), HH-1);
    int y1c = min(max(y0+1, 0), HH-1);
    int x0c = min(max(x0,   0), WW-1);
    int x1c = min(max(x0+1, 0), WW-1);

    float m00 = (vy0 && vx0) ? (1.f-wy)*(1.f-wx) : 0.f;
    float m01 = (vy0 && vx1) ? (1.f-wy)*wx       : 0.f;
    float m10 = (vy1 && vx0) ? wy*(1.f-wx)       : 0.f;
    float m11 = (vy1 && vx1) ? wy*wx             : 0.f;

    int i00 = y0c*WW + x0c, i01 = y0c*WW + x1c;
    int i10 = y1c*WW + x0c, i11 = y1c*WW + x1c;

    #pragma unroll
    for (int cg = 0; cg < 8; cg++) {
        const float* xp = x + (long)(b*CC + dgi*8 + cg)*HWHW;
        float v = m00*xp[i00] + m01*xp[i01] + m10*xp[i10] + m11*xp[i11];
        g_val[((long)(b*CC + dgi*8 + cg)*NK2 + k)*HWHW + p] = v * mk;
    }
}

// ---------------------------------------------------------------------------
extern "C" void kernel_launch(void* const* d_in, const int* in_sizes, int n_in,
                              void* d_out, int out_size)
{
    const float* x    = (const float*)d_in[0];
    const float* exf  = (const float*)d_in[1];
    const float* f1   = (const float*)d_in[2];
    const float* f2   = (const float*)d_in[3];
    const float* wgt  = (const float*)d_in[4];
    const float* bias = (const float*)d_in[5];
    const float* cb0  = (const float*)d_in[7];
    const float* cw1  = (const float*)d_in[8];
    const float* cb1  = (const float*)d_in[9];
    const float* cw2  = (const float*)d_in[10];
    const float* cb2  = (const float*)d_in[11];
    const float* cw3  = (const float*)d_in[12];
    const float* cb3  = (const float*)d_in[13];
    const float* cw0  = (const float*)d_in[6];
    float* out = (float*)d_out;

    void *p_ef, *p_A, *p_B, *p_h3, *p_val, *p_w0p;
    cudaGetSymbolAddress(&p_ef,  g_ef);
    cudaGetSymbolAddress(&p_A,   g_bufA);
    cudaGetSymbolAddress(&p_B,   g_bufB);
    cudaGetSymbolAddress(&p_h3,  g_h3);
    cudaGetSymbolAddress(&p_val, g_val);
    cudaGetSymbolAddress(&p_w0p, g_w0p);

    pack_ef_k<<<(BB*CIN0P*HWHW + 255)/256, 256>>>(exf, f1, f2);
    pad_w0_k<<<(CC*CIN0P*9 + 255)/256, 256>>>(cw0);

    dim3 g128(WW/16, HH/8, BB * ((128 + 63)/64));   // 10 x 12 x 4
    conv_k<3, true ><<<g128, 256>>>((const float*)p_ef, (const float*)p_w0p, cb0,
                                    (float*)p_A, CIN0P, 128);
    conv_k<3, true ><<<g128, 256>>>((const float*)p_A, cw1, cb1,
                                    (float*)p_B, 128, 128);
    conv_k<3, true ><<<g128, 256>>>((const float*)p_B, cw2, cb2,
                                    (float*)p_A, 128, 128);

    dim3 g432(WW/16, HH/8, BB * ((COFF + 63)/64));  // 10 x 12 x 14
    conv_k<3, false><<<g432, 256>>>((const float*)p_A, cw3, cb3,
                                    (float*)p_h3, 128, COFF);

    gather_k<<<(BB*NDG*NK2*HWHW + 255)/256, 256>>>(x, f1, f2);

    conv_k<1, false><<<g128, 256>>>((const float*)p_val, wgt, bias,
                                    out, CC*NK2, 128);
}